// round 15
// baseline (speedup 1.0000x reference)
#include <cuda_runtime.h>
#include <math.h>

typedef unsigned long long u64;

#define B_DIM 8
#define H_DIM 16
#define N_PTS 1024

__device__ float g_part[128][16];   // [ (b,itile) ][ head ] partial row-sums
__device__ float g_cm[B_DIM][3];

__device__ __forceinline__ u64 pk2(float lo, float hi) {
    u64 r; asm("mov.b64 %0, {%1,%2};" : "=l"(r) : "f"(lo), "f"(hi)); return r;
}
__device__ __forceinline__ u64 ffma2(u64 a, u64 b, u64 c) {
    u64 d; asm("fma.rn.f32x2 %0, %1, %2, %3;" : "=l"(d) : "l"(a), "l"(b), "l"(c)); return d;
}
__device__ __forceinline__ void unpk2(u64 v, float& lo, float& hi) {
    asm("mov.b64 {%0,%1}, %2;" : "=f"(lo), "=f"(hi) : "l"(v));
}

// Block = (batch, 64-row i-tile); 256 threads = 16 igroups (4 rows each)
// x 2 headgroups (8 heads) x 8 j-slices (64 packs each).
// Identity: |refl_i - s_j|^2 = |s_i - s_j|^2 + 4 p_i p_j,  p = n.s + d.
// Each j-pack's 96B of broadcast LDS serves 64 pair-distances
// (4 rows x 8 heads x 2 j). 256 threads => 255-reg cap lets R=4 fit.
// sde = 2*mean_i min_j d2 (reflection isometry collapses both directions).
__global__ void __launch_bounds__(256)
chamfer_kernel(const float* __restrict__ y_pred, const float* __restrict__ sp)
{
    const int bh    = blockIdx.x;
    const int b     = bh >> 4;           // batch
    const int itile = bh & 15;           // 64-row tile
    const int t     = threadIdx.x;
    const int ig    = t & 15;            // row group (rows 4ig..4ig+3)
    const int hg    = (t >> 4) & 1;      // head group (heads hg*8..+7)
    const int js    = t >> 5;            // j slice (64 packs)

    __shared__ ulonglong2 shA[513];      // {x0,x1, y0,y1} packed point pairs (+pad)
    __shared__ ulonglong2 shB[513];      // {z0,z1, ss0,ss1}
    __shared__ u64  ptab[513 * 16];      // [jp*16 + h] : {p_h(2jp), p_h(2jp+1)}
    __shared__ float nh4[16][4];         // normalized plane (nx,ny,nz,d)
    __shared__ float ssv[64];            // ss per row of this i-tile
    __shared__ float ws[24];             // centroid warp partials

    const float* pb = sp + b * (N_PTS * 3);

    // ---- phase 1: pack point table (2 chunks of 256 threads) ----
    {
        float cx = 0.f, cy = 0.f, cz = 0.f;
        #pragma unroll
        for (int c = 0; c < 2; ++c) {
            const int tt = t + c * 256;
            const float2* pb2 = (const float2*)pb;
            float2 q0 = pb2[3 * tt + 0];
            float2 q1 = pb2[3 * tt + 1];
            float2 q2 = pb2[3 * tt + 2];
            float x0 = q0.x, y0 = q0.y, z0 = q1.x;
            float x1 = q1.y, y1 = q2.x, z1 = q2.y;
            float s0 = fmaf(x0, x0, fmaf(y0, y0, z0 * z0));
            float s1 = fmaf(x1, x1, fmaf(y1, y1, z1 * z1));
            float4 va; va.x = x0; va.y = x1; va.z = y0; va.w = y1;
            float4 vb; vb.x = z0; vb.y = z1; vb.z = s0; vb.w = s1;
            ((float4*)shA)[tt] = va;
            ((float4*)shB)[tt] = vb;
            if (tt == 0) {               // pad (prefetch target only, never computed)
                ((float4*)shA)[512] = va;
                ((float4*)shB)[512] = vb;
            }
            cx += x0 + x1; cy += y0 + y1; cz += z0 + z1;
        }
        if (itile == 0) {
            #pragma unroll
            for (int o = 16; o > 0; o >>= 1) {
                cx += __shfl_down_sync(0xffffffffu, cx, o);
                cy += __shfl_down_sync(0xffffffffu, cy, o);
                cz += __shfl_down_sync(0xffffffffu, cz, o);
            }
            if ((t & 31) == 0) {
                int w = t >> 5;
                ws[w] = cx; ws[8 + w] = cy; ws[16 + w] = cz;
            }
        }
    }
    // normalized planes (warp 0, lanes 0..15)
    if (t < 16) {
        const float* yp = y_pred + 4 * (b * H_DIM + t);
        float nx = yp[0], ny = yp[1], nz = yp[2], pd = yp[3];
        float inv = 1.0f / sqrtf(nx * nx + ny * ny + nz * nz);
        nh4[t][0] = nx * inv; nh4[t][1] = ny * inv; nh4[t][2] = nz * inv; nh4[t][3] = pd;
    }
    __syncthreads();

    if (itile == 0 && t == 0) {
        float cx = 0, cy = 0, cz = 0;
        #pragma unroll
        for (int w = 0; w < 8; ++w) { cx += ws[w]; cy += ws[8 + w]; cz += ws[16 + w]; }
        g_cm[b][0] = cx * (1.0f / N_PTS);
        g_cm[b][1] = cy * (1.0f / N_PTS);
        g_cm[b][2] = cz * (1.0f / N_PTS);
    }

    // ---- phase 2: fill projection table ptab[jp][h] (2 heads/thread) ----
    {
        const int ln = t & 31;
        #pragma unroll
        for (int hc = 0; hc < 2; ++hc) {
            const int hh = (t >> 5) + hc * 8;    // head 0..15
            u64 nxp = pk2(nh4[hh][0], nh4[hh][0]);
            u64 nyp = pk2(nh4[hh][1], nh4[hh][1]);
            u64 nzp = pk2(nh4[hh][2], nh4[hh][2]);
            u64 dp  = pk2(nh4[hh][3], nh4[hh][3]);
            #pragma unroll
            for (int rep = 0; rep < 16; ++rep) {
                int jp = ln + rep * 32;
                ulonglong2 A = shA[jp];
                ulonglong2 Bv = shB[jp];
                u64 p = ffma2(nzp, Bv.x, dp);
                p = ffma2(nyp, A.y, p);
                p = ffma2(nxp, A.x, p);
                ptab[jp * 16 + hh] = p;
            }
        }
    }

    // ---- per-thread row constants: rows 4ig..4ig+3 of this i-tile ----
    const int r0 = itile * 64 + ig * 4;
    u64 m2x[4], m2y[4], m2z[4], p4[4][8];
    float ssr[4];
    #pragma unroll
    for (int r = 0; r < 4; ++r) {
        float sx = pb[3 * (r0 + r) + 0];
        float sy = pb[3 * (r0 + r) + 1];
        float sz = pb[3 * (r0 + r) + 2];
        ssr[r] = fmaf(sx, sx, fmaf(sy, sy, sz * sz));
        m2x[r] = pk2(-2.0f * sx, -2.0f * sx);
        m2y[r] = pk2(-2.0f * sy, -2.0f * sy);
        m2z[r] = pk2(-2.0f * sz, -2.0f * sz);
        #pragma unroll
        for (int k = 0; k < 8; ++k) {
            int h = hg * 8 + k;
            float p = fmaf(nh4[h][0], sx, fmaf(nh4[h][1], sy, fmaf(nh4[h][2], sz, nh4[h][3])));
            p4[r][k] = pk2(4.0f * p, 4.0f * p);
        }
    }
    if (t < 16) {                        // ig==t, hg==0, js==0
        #pragma unroll
        for (int r = 0; r < 4; ++r) ssv[t * 4 + r] = ssr[r];
    }
    __syncthreads();

    // ---- mainloop: 64 j-packs, software-pipelined prefetch ----
    const float INF = __int_as_float(0x7f800000);
    float m[4][8];
    #pragma unroll
    for (int r = 0; r < 4; ++r)
        #pragma unroll
        for (int k = 0; k < 8; ++k) m[r][k] = INF;

    const int jbeg = js << 6;
    ulonglong2 A  = shA[jbeg];
    ulonglong2 Bv = shB[jbeg];
    const ulonglong2* pr0 = (const ulonglong2*)&ptab[jbeg * 16 + hg * 8];
    ulonglong2 q0 = pr0[0], q1 = pr0[1], q2 = pr0[2], q3 = pr0[3];

    #pragma unroll 2
    for (int jj = 0; jj < 64; ++jj) {
        const int jpn = jbeg + jj + 1;
        ulonglong2 An = shA[jpn];
        ulonglong2 Bn = shB[jpn];
        const ulonglong2* prn = (const ulonglong2*)&ptab[jpn * 16 + hg * 8];
        ulonglong2 qn0 = prn[0], qn1 = prn[1], qn2 = prn[2], qn3 = prn[3];

        u64 vv[4];
        #pragma unroll
        for (int r = 0; r < 4; ++r) {
            u64 v = ffma2(m2z[r], Bv.x, Bv.y);
            v = ffma2(m2y[r], A.y, v);
            vv[r] = ffma2(m2x[r], A.x, v);
        }
        u64 qa[8];
        qa[0] = q0.x; qa[1] = q0.y; qa[2] = q1.x; qa[3] = q1.y;
        qa[4] = q2.x; qa[5] = q2.y; qa[6] = q3.x; qa[7] = q3.y;
        #pragma unroll
        for (int k = 0; k < 8; ++k) {
            #pragma unroll
            for (int r = 0; r < 4; ++r) {
                float l, h;
                unpk2(ffma2(p4[r][k], qa[k], vv[r]), l, h);
                m[r][k] = fminf(m[r][k], fminf(l, h));
            }
        }
        A = An; Bv = Bn; q0 = qn0; q1 = qn1; q2 = qn2; q3 = qn3;
    }
    __syncthreads();

    // ---- stage 0: publish per-thread mins into dead ptab ----
    float* red = (float*)ptab;           // [8 slices][32 groups][32 vals] = 32KB
    {
        const int grp = ig * 2 + hg;
        float4* d = (float4*)&red[(js * 32 + grp) * 32];
        #pragma unroll
        for (int r = 0; r < 4; ++r) {
            d[r * 2 + 0] = make_float4(m[r][0], m[r][1], m[r][2], m[r][3]);
            d[r * 2 + 1] = make_float4(m[r][4], m[r][5], m[r][6], m[r][7]);
        }
    }
    __syncthreads();

    // ---- stage A: min over 8 slices -> sm2[row][head] ----
    float* sm2 = red + 8192;             // [64][16] floats
    {
        const int grp = t >> 3, q = t & 7;
        float4 mv = *(const float4*)&red[(0 * 32 + grp) * 32 + q * 4];
        #pragma unroll
        for (int s = 1; s < 8; ++s) {
            float4 x = *(const float4*)&red[(s * 32 + grp) * 32 + q * 4];
            mv.x = fminf(mv.x, x.x); mv.y = fminf(mv.y, x.y);
            mv.z = fminf(mv.z, x.z); mv.w = fminf(mv.w, x.w);
        }
        const int gi = grp >> 1, hgrp = grp & 1;
        const int row = gi * 4 + (q >> 1);
        const int hb  = hgrp * 8 + (q & 1) * 4;
        *(float4*)&sm2[row * 16 + hb] = mv;
    }
    __syncthreads();

    // ---- stage B: sum (ss_r + min) over 64 rows per head ----
    {
        const int h = t >> 4, c = t & 15;
        float s = 0.f;
        #pragma unroll
        for (int i = 0; i < 4; ++i) {
            const int r = c * 4 + i;
            s += ssv[r] + sm2[r * 16 + h];
        }
        #pragma unroll
        for (int o = 8; o > 0; o >>= 1)
            s += __shfl_down_sync(0xffffffffu, s, o, 16);
        if (c == 0) g_part[bh][h] = s;
    }
}

// One block, 128 threads (proven structure): thread t = (b,h).
// sde assembled deterministically from the 16 i-tile partials.
__global__ void __launch_bounds__(128, 1)
final_kernel(const float* __restrict__ y_pred, float* __restrict__ out)
{
    const int t  = threadIdx.x;
    const int eb = t >> 4;
    const int eh = t & 15;

    __shared__ float hnx[128], hny[128], hnz[128], hsd[128], hkey[128];

    const float* ypp = y_pred + 4 * t;
    float nx = ypp[0], ny = ypp[1], nz = ypp[2], pd = ypp[3];
    float iv = 1.0f / sqrtf(nx * nx + ny * ny + nz * nz);
    nx *= iv; ny *= iv; nz *= iv;

    float acc = 0.0f;
    #pragma unroll
    for (int it = 0; it < 16; ++it) acc += g_part[eb * 16 + it][eh];
    float sde = 2.0f * (acc * (1.0f / 1024.0f));

    hnx[t] = nx; hny[t] = ny; hnz[t] = nz; hsd[t] = sde;
    __syncthreads();

    const int base = eb * H_DIM;
    float mn = hsd[base], mx = hsd[base];
    #pragma unroll
    for (int g2 = 1; g2 < H_DIM; ++g2) {
        mn = fminf(mn, hsd[base + g2]); mx = fmaxf(mx, hsd[base + g2]);
    }
    float conf = 1.0f - (sde - mn) / fabsf(mx - mn);

    // (ang<30 || 180-ang<30)  <=>  |cos| > cos(30deg)  (acos monotone)
    const float COS30 = 0.86602540378443864676f;
    bool valid = (sde <= 10.0f);
    bool any = false;
    #pragma unroll
    for (int g2 = 0; g2 < H_DIM; ++g2) {
        if (g2 == eh) continue;
        float c = nx * hnx[base + g2] + ny * hny[base + g2] + nz * hnz[base + g2];
        c = fminf(1.0f, fmaxf(-1.0f, c));
        if (fabsf(c) > COS30 && (hsd[base + g2] <= 10.0f) && (sde >= hsd[base + g2]))
            any = true;
    }
    bool keep = valid && !any;
    hkey[t] = keep ? conf : __int_as_float(0xff800000);
    __syncthreads();

    float key = hkey[t];
    int rank = 0;
    #pragma unroll
    for (int g2 = 0; g2 < H_DIM; ++g2) {
        float kg = hkey[base + g2];
        if (kg > key || (kg == key && g2 < eh)) rank++;
    }
    float* o = out + (base + rank) * 8;
    if (keep) {
        float cx = g_cm[eb][0], cy = g_cm[eb][1], cz = g_cm[eb][2];
        float pj = fmaf(nx, cx, fmaf(ny, cy, fmaf(nz, cz, pd)));
        o[0] = nx; o[1] = ny; o[2] = nz;
        o[3] = cx - pj * nx;
        o[4] = cy - pj * ny;
        o[5] = cz - pj * nz;
        o[6] = conf;
        o[7] = sde;
    } else {
        #pragma unroll
        for (int c = 0; c < 8; ++c) o[c] = 0.0f;
    }
}

extern "C" void kernel_launch(void* const* d_in, const int* in_sizes, int n_in,
                              void* d_out, int out_size)
{
    const float* y_pred = (const float*)d_in[0];   // (8,16,4)
    const float* sp     = (const float*)d_in[1];   // (8,1024,3)
    float* out          = (float*)d_out;           // (8,16,8)

    chamfer_kernel<<<B_DIM * H_DIM, 256>>>(y_pred, sp);
    final_kernel<<<1, 128>>>(y_pred, out);
}

// round 16
// speedup vs baseline: 1.5714x; 1.5714x over previous
#include <cuda_runtime.h>
#include <math.h>

typedef unsigned long long u64;

#define B_DIM 8
#define H_DIM 16
#define N_PTS 1024

__device__ float g_part[128][16];   // [ (b,itile) ][ head ] partial row-sums
__device__ float g_cm[B_DIM][3];

__device__ __forceinline__ u64 pk2(float lo, float hi) {
    u64 r; asm("mov.b64 %0, {%1,%2};" : "=l"(r) : "f"(lo), "f"(hi)); return r;
}
__device__ __forceinline__ u64 ffma2(u64 a, u64 b, u64 c) {
    u64 d; asm("fma.rn.f32x2 %0, %1, %2, %3;" : "=l"(d) : "l"(a), "l"(b), "l"(c)); return d;
}
__device__ __forceinline__ void unpk2(u64 v, float& lo, float& hi) {
    asm("mov.b64 {%0,%1}, %2;" : "=f"(lo), "=f"(hi) : "l"(v));
}

// Block = (batch, 64-row i-tile); 256 threads = 16 igroups (4 rows each)
// x 2 headgroups (8 heads) x 8 j-slices (64 packs each).
// Identity: |refl_i - s_j|^2 = |s_i - s_j|^2 + 4 p_i p_j,  p = n.s + d.
// Each j-pack's 96B of broadcast LDS serves 64 pair-distances
// (4 rows x 8 heads x 2 j). 256 threads => 255-reg cap lets R=4 fit.
// sde = 2*mean_i min_j d2 (reflection isometry collapses both directions).
__global__ void __launch_bounds__(256)
chamfer_kernel(const float* __restrict__ y_pred, const float* __restrict__ sp)
{
    const int bh    = blockIdx.x;
    const int b     = bh >> 4;           // batch
    const int itile = bh & 15;           // 64-row tile
    const int t     = threadIdx.x;
    const int ig    = t & 15;            // row group (rows 4ig..4ig+3)
    const int hg    = (t >> 4) & 1;      // head group (heads hg*8..+7)
    const int js    = t >> 5;            // j slice (64 packs)

    __shared__ ulonglong2 shA[513];      // {x0,x1, y0,y1} packed point pairs (+pad)
    __shared__ ulonglong2 shB[513];      // {z0,z1, ss0,ss1}
    __shared__ u64  ptab[513 * 16];      // [jp*16 + h] : {p_h(2jp), p_h(2jp+1)}
    __shared__ float nh4[16][4];         // normalized plane (nx,ny,nz,d)
    __shared__ float ssv[64];            // ss per row of this i-tile
    __shared__ float ws[24];             // centroid warp partials

    const float* pb = sp + b * (N_PTS * 3);

    // ---- phase 1: pack point table (2 chunks of 256 threads) ----
    {
        float cx = 0.f, cy = 0.f, cz = 0.f;
        #pragma unroll
        for (int c = 0; c < 2; ++c) {
            const int tt = t + c * 256;
            const float2* pb2 = (const float2*)pb;
            float2 q0 = pb2[3 * tt + 0];
            float2 q1 = pb2[3 * tt + 1];
            float2 q2 = pb2[3 * tt + 2];
            float x0 = q0.x, y0 = q0.y, z0 = q1.x;
            float x1 = q1.y, y1 = q2.x, z1 = q2.y;
            float s0 = fmaf(x0, x0, fmaf(y0, y0, z0 * z0));
            float s1 = fmaf(x1, x1, fmaf(y1, y1, z1 * z1));
            float4 va; va.x = x0; va.y = x1; va.z = y0; va.w = y1;
            float4 vb; vb.x = z0; vb.y = z1; vb.z = s0; vb.w = s1;
            ((float4*)shA)[tt] = va;
            ((float4*)shB)[tt] = vb;
            if (tt == 0) {               // pad (prefetch target only, never computed)
                ((float4*)shA)[512] = va;
                ((float4*)shB)[512] = vb;
            }
            cx += x0 + x1; cy += y0 + y1; cz += z0 + z1;
        }
        if (itile == 0) {
            #pragma unroll
            for (int o = 16; o > 0; o >>= 1) {
                cx += __shfl_down_sync(0xffffffffu, cx, o);
                cy += __shfl_down_sync(0xffffffffu, cy, o);
                cz += __shfl_down_sync(0xffffffffu, cz, o);
            }
            if ((t & 31) == 0) {
                int w = t >> 5;
                ws[w] = cx; ws[8 + w] = cy; ws[16 + w] = cz;
            }
        }
    }
    // normalized planes (warp 0, lanes 0..15)
    if (t < 16) {
        const float* yp = y_pred + 4 * (b * H_DIM + t);
        float nx = yp[0], ny = yp[1], nz = yp[2], pd = yp[3];
        float inv = 1.0f / sqrtf(nx * nx + ny * ny + nz * nz);
        nh4[t][0] = nx * inv; nh4[t][1] = ny * inv; nh4[t][2] = nz * inv; nh4[t][3] = pd;
    }
    __syncthreads();

    if (itile == 0 && t == 0) {
        float cx = 0, cy = 0, cz = 0;
        #pragma unroll
        for (int w = 0; w < 8; ++w) { cx += ws[w]; cy += ws[8 + w]; cz += ws[16 + w]; }
        g_cm[b][0] = cx * (1.0f / N_PTS);
        g_cm[b][1] = cy * (1.0f / N_PTS);
        g_cm[b][2] = cz * (1.0f / N_PTS);
    }

    // ---- phase 2: fill projection table ptab[jp][h] (2 heads/thread) ----
    {
        const int ln = t & 31;
        #pragma unroll
        for (int hc = 0; hc < 2; ++hc) {
            const int hh = (t >> 5) + hc * 8;    // head 0..15
            u64 nxp = pk2(nh4[hh][0], nh4[hh][0]);
            u64 nyp = pk2(nh4[hh][1], nh4[hh][1]);
            u64 nzp = pk2(nh4[hh][2], nh4[hh][2]);
            u64 dp  = pk2(nh4[hh][3], nh4[hh][3]);
            #pragma unroll
            for (int rep = 0; rep < 16; ++rep) {
                int jp = ln + rep * 32;
                ulonglong2 A = shA[jp];
                ulonglong2 Bv = shB[jp];
                u64 p = ffma2(nzp, Bv.x, dp);
                p = ffma2(nyp, A.y, p);
                p = ffma2(nxp, A.x, p);
                ptab[jp * 16 + hh] = p;
            }
        }
    }

    // ---- per-thread row constants: rows 4ig..4ig+3 of this i-tile ----
    const int r0 = itile * 64 + ig * 4;
    u64 m2x[4], m2y[4], m2z[4], p4[4][8];
    float ssr[4];
    #pragma unroll
    for (int r = 0; r < 4; ++r) {
        float sx = pb[3 * (r0 + r) + 0];
        float sy = pb[3 * (r0 + r) + 1];
        float sz = pb[3 * (r0 + r) + 2];
        ssr[r] = fmaf(sx, sx, fmaf(sy, sy, sz * sz));
        m2x[r] = pk2(-2.0f * sx, -2.0f * sx);
        m2y[r] = pk2(-2.0f * sy, -2.0f * sy);
        m2z[r] = pk2(-2.0f * sz, -2.0f * sz);
        #pragma unroll
        for (int k = 0; k < 8; ++k) {
            int h = hg * 8 + k;
            float p = fmaf(nh4[h][0], sx, fmaf(nh4[h][1], sy, fmaf(nh4[h][2], sz, nh4[h][3])));
            p4[r][k] = pk2(4.0f * p, 4.0f * p);
        }
    }
    if (t < 16) {                        // ig==t, hg==0, js==0
        #pragma unroll
        for (int r = 0; r < 4; ++r) ssv[t * 4 + r] = ssr[r];
    }
    __syncthreads();

    // ---- mainloop: 64 j-packs, software-pipelined prefetch ----
    const float INF = __int_as_float(0x7f800000);
    float m[4][8];
    #pragma unroll
    for (int r = 0; r < 4; ++r)
        #pragma unroll
        for (int k = 0; k < 8; ++k) m[r][k] = INF;

    const int jbeg = js << 6;
    ulonglong2 A  = shA[jbeg];
    ulonglong2 Bv = shB[jbeg];
    const ulonglong2* pr0 = (const ulonglong2*)&ptab[jbeg * 16 + hg * 8];
    ulonglong2 q0 = pr0[0], q1 = pr0[1], q2 = pr0[2], q3 = pr0[3];

    #pragma unroll 2
    for (int jj = 0; jj < 64; ++jj) {
        const int jpn = jbeg + jj + 1;
        ulonglong2 An = shA[jpn];
        ulonglong2 Bn = shB[jpn];
        const ulonglong2* prn = (const ulonglong2*)&ptab[jpn * 16 + hg * 8];
        ulonglong2 qn0 = prn[0], qn1 = prn[1], qn2 = prn[2], qn3 = prn[3];

        u64 vv[4];
        #pragma unroll
        for (int r = 0; r < 4; ++r) {
            u64 v = ffma2(m2z[r], Bv.x, Bv.y);
            v = ffma2(m2y[r], A.y, v);
            vv[r] = ffma2(m2x[r], A.x, v);
        }
        u64 qa[8];
        qa[0] = q0.x; qa[1] = q0.y; qa[2] = q1.x; qa[3] = q1.y;
        qa[4] = q2.x; qa[5] = q2.y; qa[6] = q3.x; qa[7] = q3.y;
        #pragma unroll
        for (int k = 0; k < 8; ++k) {
            #pragma unroll
            for (int r = 0; r < 4; ++r) {
                float l, h;
                unpk2(ffma2(p4[r][k], qa[k], vv[r]), l, h);
                m[r][k] = fminf(m[r][k], fminf(l, h));
            }
        }
        A = An; Bv = Bn; q0 = qn0; q1 = qn1; q2 = qn2; q3 = qn3;
    }
    __syncthreads();

    // ---- stage 0: publish per-thread mins into dead ptab ----
    float* red = (float*)ptab;           // [8 slices][32 groups][32 vals] = 32KB
    {
        const int grp = ig * 2 + hg;
        float4* d = (float4*)&red[(js * 32 + grp) * 32];
        #pragma unroll
        for (int r = 0; r < 4; ++r) {
            d[r * 2 + 0] = make_float4(m[r][0], m[r][1], m[r][2], m[r][3]);
            d[r * 2 + 1] = make_float4(m[r][4], m[r][5], m[r][6], m[r][7]);
        }
    }
    __syncthreads();

    // ---- stage A: min over 8 slices -> sm2[row][head] ----
    float* sm2 = red + 8192;             // [64][16] floats
    {
        const int grp = t >> 3, q = t & 7;
        float4 mv = *(const float4*)&red[(0 * 32 + grp) * 32 + q * 4];
        #pragma unroll
        for (int s = 1; s < 8; ++s) {
            float4 x = *(const float4*)&red[(s * 32 + grp) * 32 + q * 4];
            mv.x = fminf(mv.x, x.x); mv.y = fminf(mv.y, x.y);
            mv.z = fminf(mv.z, x.z); mv.w = fminf(mv.w, x.w);
        }
        const int gi = grp >> 1, hgrp = grp & 1;
        const int row = gi * 4 + (q >> 1);
        const int hb  = hgrp * 8 + (q & 1) * 4;
        *(float4*)&sm2[row * 16 + hb] = mv;
    }
    __syncthreads();

    // ---- stage B: sum (ss_r + min) over 64 rows per head ----
    {
        const int h = t >> 4, c = t & 15;
        float s = 0.f;
        #pragma unroll
        for (int i = 0; i < 4; ++i) {
            const int r = c * 4 + i;
            s += ssv[r] + sm2[r * 16 + h];
        }
        #pragma unroll
        for (int o = 8; o > 0; o >>= 1)
            s += __shfl_down_sync(0xffffffffu, s, o, 16);
        if (c == 0) g_part[bh][h] = s;
    }
}

// One block, 128 threads (proven structure): thread t = (b,h).
// sde assembled deterministically from the 16 i-tile partials.
__global__ void __launch_bounds__(128, 1)
final_kernel(const float* __restrict__ y_pred, float* __restrict__ out)
{
    const int t  = threadIdx.x;
    const int eb = t >> 4;
    const int eh = t & 15;

    __shared__ float hnx[128], hny[128], hnz[128], hsd[128], hkey[128];

    const float* ypp = y_pred + 4 * t;
    float nx = ypp[0], ny = ypp[1], nz = ypp[2], pd = ypp[3];
    float iv = 1.0f / sqrtf(nx * nx + ny * ny + nz * nz);
    nx *= iv; ny *= iv; nz *= iv;

    float acc = 0.0f;
    #pragma unroll
    for (int it = 0; it < 16; ++it) acc += g_part[eb * 16 + it][eh];
    float sde = 2.0f * (acc * (1.0f / 1024.0f));

    hnx[t] = nx; hny[t] = ny; hnz[t] = nz; hsd[t] = sde;
    __syncthreads();

    const int base = eb * H_DIM;
    float mn = hsd[base], mx = hsd[base];
    #pragma unroll
    for (int g2 = 1; g2 < H_DIM; ++g2) {
        mn = fminf(mn, hsd[base + g2]); mx = fmaxf(mx, hsd[base + g2]);
    }
    float conf = 1.0f - (sde - mn) / fabsf(mx - mn);

    // (ang<30 || 180-ang<30)  <=>  |cos| > cos(30deg)  (acos monotone)
    const float COS30 = 0.86602540378443864676f;
    bool valid = (sde <= 10.0f);
    bool any = false;
    #pragma unroll
    for (int g2 = 0; g2 < H_DIM; ++g2) {
        if (g2 == eh) continue;
        float c = nx * hnx[base + g2] + ny * hny[base + g2] + nz * hnz[base + g2];
        c = fminf(1.0f, fmaxf(-1.0f, c));
        if (fabsf(c) > COS30 && (hsd[base + g2] <= 10.0f) && (sde >= hsd[base + g2]))
            any = true;
    }
    bool keep = valid && !any;
    hkey[t] = keep ? conf : __int_as_float(0xff800000);
    __syncthreads();

    float key = hkey[t];
    int rank = 0;
    #pragma unroll
    for (int g2 = 0; g2 < H_DIM; ++g2) {
        float kg = hkey[base + g2];
        if (kg > key || (kg == key && g2 < eh)) rank++;
    }
    float* o = out + (base + rank) * 8;
    if (keep) {
        float cx = g_cm[eb][0], cy = g_cm[eb][1], cz = g_cm[eb][2];
        float pj = fmaf(nx, cx, fmaf(ny, cy, fmaf(nz, cz, pd)));
        o[0] = nx; o[1] = ny; o[2] = nz;
        o[3] = cx - pj * nx;
        o[4] = cy - pj * ny;
        o[5] = cz - pj * nz;
        o[6] = conf;
        o[7] = sde;
    } else {
        #pragma unroll
        for (int c = 0; c < 8; ++c) o[c] = 0.0f;
    }
}

extern "C" void kernel_launch(void* const* d_in, const int* in_sizes, int n_in,
                              void* d_out, int out_size)
{
    const float* y_pred = (const float*)d_in[0];   // (8,16,4)
    const float* sp     = (const float*)d_in[1];   // (8,1024,3)
    float* out          = (float*)d_out;           // (8,16,8)

    chamfer_kernel<<<B_DIM * H_DIM, 256>>>(y_pred, sp);
    final_kernel<<<1, 128>>>(y_pred, out);
}